// round 17
// baseline (speedup 1.0000x reference)
#include <cuda_runtime.h>
#include <cuda_fp16.h>
#include <cstdint>

#define BATCH 8
#define SEQ   4096
#define CDIM  768
#define HDIM  64
#define SPLITS 4
#define NT    (SEQ / (64 * SPLITS))   // kv tiles per block

// Scratch
__device__ uint32_t g_qh[BATCH * SEQ * 32];        // q fp16x2, sqrt(scale*log2e) folded
__device__ uint32_t g_kh[BATCH * SEQ * 32];        // k fp16x2, sqrt(scale*log2e) folded
__device__ uint32_t g_vTh[BATCH * HDIM * (SEQ/2)]; // v fp16x2 transposed, pairs along t
__device__ uint32_t g_opart[SPLITS * BATCH * SEQ * 32];  // O partial fp16x2 pairs
__device__ float    g_lpart[SPLITS * BATCH * SEQ];
__device__ uint32_t g_wT[192 * 384];               // W^T fp16x2 [n][kpair]

// ---------------------------------------------------------------------------
__device__ __forceinline__ void mma_f16(float c[4], const uint32_t a[4], const uint32_t b[2]) {
    asm volatile(
        "mma.sync.aligned.m16n8k16.row.col.f32.f16.f16.f32 "
        "{%0,%1,%2,%3}, {%4,%5,%6,%7}, {%8,%9}, {%0,%1,%2,%3};"
        : "+f"(c[0]), "+f"(c[1]), "+f"(c[2]), "+f"(c[3])
        : "r"(a[0]), "r"(a[1]), "r"(a[2]), "r"(a[3]), "r"(b[0]), "r"(b[1]));
}

__device__ __forceinline__ void ldsm_x4(uint32_t& r0, uint32_t& r1, uint32_t& r2,
                                        uint32_t& r3, uint32_t addr) {
    asm volatile("ldmatrix.sync.aligned.m8n8.x4.shared.b16 {%0,%1,%2,%3}, [%4];"
                 : "=r"(r0), "=r"(r1), "=r"(r2), "=r"(r3) : "r"(addr));
}

__device__ __forceinline__ uint32_t packh(float a, float b) {
    __half2 h = __floats2half2_rn(a, b);
    return *reinterpret_cast<uint32_t*>(&h);
}

__device__ __forceinline__ uint32_t hadd2(uint32_t a, uint32_t b) {
    uint32_t d;
    asm("add.f16x2 %0, %1, %2;" : "=r"(d) : "r"(a), "r"(b));
    return d;
}

__device__ __forceinline__ float2 unpackh(uint32_t u) {
    __half2 h = *reinterpret_cast<__half2*>(&u);
    return __half22float2(h);
}

// pack fp32 pair -> fp16x2, clamp at 15.5, exp2 in one f16x2 MUFU
__device__ __forceinline__ uint32_t hex2(float a, float b) {
    uint32_t u = packh(a, b);
    asm("min.f16x2 %0, %0, %1;" : "+r"(u) : "r"(0x4BC04BC0u));  // 15.5, 15.5
    asm("ex2.approx.f16x2 %0, %0;" : "+r"(u));
    return u;
}

__device__ __forceinline__ uint32_t smem_u32(const void* p) {
    uint32_t a;
    asm("{ .reg .u64 t; cvta.to.shared.u64 t, %1; cvt.u32.u64 %0, t; }"
        : "=r"(a) : "l"(p));
    return a;
}

__device__ __forceinline__ void cp16(uint32_t dst, const void* src) {
    asm volatile("cp.async.ca.shared.global [%0], [%1], 16;"
                 :: "r"(dst), "l"(src) : "memory");
}
#define CP_COMMIT() asm volatile("cp.async.commit_group;" ::: "memory")
#define CP_WAIT(n)  asm volatile("cp.async.wait_group %0;" :: "n"(n) : "memory")

// ---------------------------------------------------------------------------
// Kernel 0: transpose+convert W into g_wT[n][kpair]
// ---------------------------------------------------------------------------
__global__ void __launch_bounds__(256) wconv_kernel(
    const float* __restrict__ Wq, const float* __restrict__ Wk,
    const float* __restrict__ Wv)
{
    int i = blockIdx.x * 256 + threadIdx.x;
    if (i >= 192 * 384) return;
    int kp = i / 192;
    int n  = i % 192;
    const float* W = (n < 64) ? Wq : (n < 128) ? Wk : Wv;
    int nn = n & 63;
    float a = W[(size_t)(2 * kp) * HDIM + nn];
    float b = W[(size_t)(2 * kp + 1) * HDIM + nn];
    g_wT[n * 384 + kp] = packh(a, b);
}

// ---------------------------------------------------------------------------
// Kernel 1: fused QKV projection, fp16 m16n8k16.
// x staged through REGISTERS (LDG 1 chunk ahead) -> packed fp16 xh (double buf).
// W via 3-deep cp.async pipeline. One __syncthreads per chunk.
// Block 128 thr (4 warps), 64 rows, k-chunk 32 (24 chunks).
// smem (u32): xh [2][64*20] | ws [3][192*20]   (~55 KB)
// ---------------------------------------------------------------------------
#define XHP 20
#define WP  20
#define WS_OFF  (2 * 64 * XHP)
#define QKV_SMEM_U32 (WS_OFF + 3 * 192 * WP)
#define QKV_SMEM (QKV_SMEM_U32 * 4)
#define VBP 66

__global__ void __launch_bounds__(128) qkv_kernel(
    const float* __restrict__ x,
    const float* __restrict__ bq, const float* __restrict__ bk,
    const float* __restrict__ bv)
{
    extern __shared__ uint32_t qsm[];
    uint32_t* xh = qsm;                      // 2 x 64 x XHP (fp16x2)
    uint32_t* ws = qsm + WS_OFF;             // 3 x 192 x WP

    const int tid  = threadIdx.x;
    const int lane = tid & 31;
    const int warp = tid >> 5;
    const int r    = lane >> 2;
    const int c    = lane & 3;
    const int jg   = warp & 1;
    const int rg   = warp >> 1;
    const int rowbase = rg * 32;
    const int j0   = jg * 12;
    const int row0 = blockIdx.x * 64;

    const int ro = (lane & 7) + ((lane >> 4) << 3);
    const int co = ((lane >> 3) & 1) << 2;
    const int ar = (lane & 15);              // A-ldsm row
    const int ac = (lane >> 4) << 2;         // A-ldsm col offset (u32)

    const uint32_t xh_base = smem_u32(xh);
    const uint32_t ws_base = smem_u32(ws);

    const int xrow = tid >> 1, xhalf = tid & 1;
    const float* xrowp = x + (size_t)(row0 + xrow) * CDIM + 16 * xhalf;

    // x chunk 0 into registers
    float4 xr[4];
#pragma unroll
    for (int i = 0; i < 4; i++)
        xr[i] = *(const float4*)&xrowp[i * 4];

    // prefetch W chunks 0 and 1 (separate commit groups)
#pragma unroll
    for (int pc = 0; pc < 2; pc++) {
        uint32_t wd = ws_base + (uint32_t)(pc * 192 * WP) * 4;
#pragma unroll
        for (int it = 0; it < 6; it++) {
            int idx = tid + it * 128;
            int n = idx >> 2, qd = idx & 3;
            cp16(wd + (uint32_t)(n * WP + qd * 4) * 4, g_wT + n * 384 + pc * 16 + qd * 4);
        }
        CP_COMMIT();
    }

    float acc0[12][4] = {};
    float acc1[12][4] = {};

    for (int ch = 0; ch < 24; ch++) {
        const int buf2 = ch & 1;
        const int buf3 = ch % 3;

        // pack x regs -> xh[buf2]  (readers of buf2 wait at the sync below;
        // prior readers of buf2 were chunk ch-2, ordered by sync of ch-1)
        {
            uint32_t* xd = xh + buf2 * 64 * XHP + xrow * XHP + xhalf * 8;
#pragma unroll
            for (int i = 0; i < 4; i++) {
                xd[i * 2]     = packh(xr[i].x, xr[i].y);
                xd[i * 2 + 1] = packh(xr[i].z, xr[i].w);
            }
        }
        if (ch < 23) { CP_WAIT(1); } else { CP_WAIT(0); }
        __syncthreads();

        // LDG x for chunk ch+1 (hidden under the mma phase)
        if (ch + 1 < 24) {
#pragma unroll
            for (int i = 0; i < 4; i++)
                xr[i] = *(const float4*)&xrowp[(ch + 1) * 32 + i * 4];
        }
        // prefetch W chunk ch+2
        if (ch + 2 < 24) {
            const int kc = (ch + 2) * 32;
            uint32_t wd = ws_base + (uint32_t)(((ch + 2) % 3) * 192 * WP) * 4;
#pragma unroll
            for (int it = 0; it < 6; it++) {
                int idx = tid + it * 128;
                int n = idx >> 2, qd = idx & 3;
                cp16(wd + (uint32_t)(n * WP + qd * 4) * 4, g_wT + n * 384 + (kc >> 1) + qd * 4);
            }
            CP_COMMIT();
        }

        const uint32_t xha = xh_base + (uint32_t)(buf2 * 64 * XHP) * 4;
        const uint32_t wsa = ws_base + (uint32_t)(buf3 * 192 * WP) * 4;
#pragma unroll
        for (int ks = 0; ks < 2; ks++) {
            uint32_t a0[4], a1[4];
            ldsm_x4(a0[0], a0[1], a0[2], a0[3],
                    xha + (uint32_t)((rowbase + ar) * XHP + ks * 8 + ac) * 4);
            ldsm_x4(a1[0], a1[1], a1[2], a1[3],
                    xha + (uint32_t)((rowbase + 16 + ar) * XHP + ks * 8 + ac) * 4);
#pragma unroll
            for (int jp = 0; jp < 6; jp++) {
                int jA = j0 + 2 * jp;
                uint32_t b0, b1, b2, b3;
                ldsm_x4(b0, b1, b2, b3,
                        wsa + (uint32_t)((jA * 8 + ro) * WP + ks * 8 + co) * 4);
                uint32_t bbA[2] = { b0, b1 };
                uint32_t bbB[2] = { b2, b3 };
                mma_f16(acc0[2 * jp],     a0, bbA);
                mma_f16(acc1[2 * jp],     a1, bbA);
                mma_f16(acc0[2 * jp + 1], a0, bbB);
                mma_f16(acc1[2 * jp + 1], a1, bbB);
            }
        }
    }

    // ---- Epilogue ----
    const float shq = sqrtf(rsqrtf((float)CDIM) * 1.4426950408889634f);

    // q, k: packed fp16 row-major (cols 0..127)
#pragma unroll
    for (int j = 0; j < 12; j++) {
        int col0 = (j0 + j) * 8 + 2 * c;
        int m    = col0 >> 6;
        if (m < 2) {
            int lc = col0 & 63;
            const float* bias = (m == 0) ? bq : bk;
            float b0v = bias[lc], b1v = bias[lc + 1];
            uint32_t* dst = (m == 0) ? g_qh : g_kh;
            size_t rw = (size_t)(row0 + rowbase + r);
            int uc = lc >> 1;
            dst[(rw)      * 32 + uc] = packh((acc0[j][0] + b0v) * shq, (acc0[j][1] + b1v) * shq);
            dst[(rw + 8)  * 32 + uc] = packh((acc0[j][2] + b0v) * shq, (acc0[j][3] + b1v) * shq);
            dst[(rw + 16) * 32 + uc] = packh((acc1[j][0] + b0v) * shq, (acc1[j][1] + b1v) * shq);
            dst[(rw + 24) * 32 + uc] = packh((acc1[j][2] + b0v) * shq, (acc1[j][3] + b1v) * shq);
        }
    }

    // v: stage fp32 into vbuf (aliases smem), then pack fp16 coalesced
    __syncthreads();                       // all chunk compute done; safe to alias
    float* vbuf = (float*)qsm;             // 64(h) x VBP(t) fp32 = 16.9 KB
    if (jg == 1) {
#pragma unroll
        for (int j = 4; j < 12; j++) {
            int col0 = (12 + j) * 8 + 2 * c;
            int lc = col0 - 128;
            float b0v = bv[lc], b1v = bv[lc + 1];
            int tl = rowbase + r;
            vbuf[lc * VBP + tl]            = acc0[j][0] + b0v;
            vbuf[(lc + 1) * VBP + tl]      = acc0[j][1] + b1v;
            vbuf[lc * VBP + tl + 8]        = acc0[j][2] + b0v;
            vbuf[(lc + 1) * VBP + tl + 8]  = acc0[j][3] + b1v;
            vbuf[lc * VBP + tl + 16]       = acc1[j][0] + b0v;
            vbuf[(lc + 1) * VBP + tl + 16] = acc1[j][1] + b1v;
            vbuf[lc * VBP + tl + 24]       = acc1[j][2] + b0v;
            vbuf[(lc + 1) * VBP + tl + 24] = acc1[j][3] + b1v;
        }
    }
    __syncthreads();
    {
        int bb    = row0 >> 12;
        int tbase = row0 & (SEQ - 1);
        uint32_t* vdst = g_vTh + (size_t)bb * HDIM * (SEQ / 2) + (tbase >> 1);
#pragma unroll
        for (int p = 0; p < 16; p++) {
            int idx = p * 128 + tid;
            int h = idx >> 5, tp = idx & 31;
            float a  = vbuf[h * VBP + 2 * tp];
            float b2 = vbuf[h * VBP + 2 * tp + 1];
            vdst[(size_t)h * (SEQ / 2) + tp] = packh(a, b2);
        }
    }
}

// ---------------------------------------------------------------------------
// Kernel 2: fp16 flash attention. ldmatrix B-frags, f16x2 exp, register P,
// l via fragment pre-sum + one ones-mma per row-pair, cp.async double-buffer.
// O partials stored packed fp16x2. Forced 3 blocks/SM.
// Block 128 thr (4 warps); q-tile 128 (32 rows/warp), kv-tile 64, SPLITS=4.
// ---------------------------------------------------------------------------
#define PB 36

__global__ void __launch_bounds__(128, 3) attn_kernel()
{
    __shared__ uint32_t ksb[2][64 * PB];
    __shared__ uint32_t vsb[2][64 * PB];

    const int tid  = threadIdx.x;
    const int lane = tid & 31;
    const int warp = tid >> 5;
    const int r    = lane >> 2;
    const int c    = lane & 3;
    const int b    = blockIdx.y;
    const int q0   = blockIdx.x * 128;
    const int split = blockIdx.z;
    const int qr   = warp * 32 + r;

    const int ro = (lane & 7) + ((lane >> 4) << 3);
    const int co = ((lane >> 3) & 1) << 2;
    const uint32_t bone = (lane < 4) ? 0x3C003C00u : 0u;   // ones col for l

    // Q fragments directly from global
    uint32_t qa[2][4][4];
    {
        const uint32_t* qg = g_qh + ((size_t)b * SEQ + q0) * 32;
#pragma unroll
        for (int kc = 0; kc < 4; kc++) {
            qa[0][kc][0] = qg[(qr)      * 32 + kc * 8 + c];
            qa[0][kc][1] = qg[(qr + 8)  * 32 + kc * 8 + c];
            qa[0][kc][2] = qg[(qr)      * 32 + kc * 8 + c + 4];
            qa[0][kc][3] = qg[(qr + 8)  * 32 + kc * 8 + c + 4];
            qa[1][kc][0] = qg[(qr + 16) * 32 + kc * 8 + c];
            qa[1][kc][1] = qg[(qr + 24) * 32 + kc * 8 + c];
            qa[1][kc][2] = qg[(qr + 16) * 32 + kc * 8 + c + 4];
            qa[1][kc][3] = qg[(qr + 24) * 32 + kc * 8 + c + 4];
        }
    }

    const int kt0 = split * (SEQ / SPLITS);
    const uint32_t* kg = g_kh  + ((size_t)b * SEQ + kt0) * 32;
    const uint32_t* vg = g_vTh + (size_t)b * HDIM * (SEQ / 2) + (kt0 >> 1);

    const uint32_t ks_base = smem_u32(&ksb[0][0]);
    const uint32_t vs_base = smem_u32(&vsb[0][0]);
    const int crow = tid >> 3;
    const int cq   = (tid & 7) * 4;

    // Stage tile 0 into buffer 0
#pragma unroll
    for (int it = 0; it < 4; it++) {
        int row = crow + it * 16;
        cp16(ks_base + (uint32_t)(row * PB + cq) * 4, kg + (size_t)row * 32 + cq);
        cp16(vs_base + (uint32_t)(row * PB + cq) * 4, vg + (size_t)row * (SEQ / 2) + cq);
    }
    CP_COMMIT();

    float o0[8][4] = {};
    float o1[8][4] = {};
    float lac0[4] = {};
    float lac1[4] = {};

    for (int t = 0; t < NT; t++) {
        const int buf = t & 1;
        CP_WAIT(0);
        __syncthreads();
        if (t + 1 < NT) {
            const uint32_t* kgn = kg + (size_t)(t + 1) * 64 * 32;
            const uint32_t* vgn = vg + (t + 1) * 32;
            uint32_t kd = ks_base + (uint32_t)((buf ^ 1) * 64 * PB) * 4;
            uint32_t vd = vs_base + (uint32_t)((buf ^ 1) * 64 * PB) * 4;
#pragma unroll
            for (int it = 0; it < 4; it++) {
                int row = crow + it * 16;
                cp16(kd + (uint32_t)(row * PB + cq) * 4, kgn + (size_t)row * 32 + cq);
                cp16(vd + (uint32_t)(row * PB + cq) * 4, vgn + (size_t)row * (SEQ / 2) + cq);
            }
            CP_COMMIT();
        }

        const uint32_t ksa = ks_base + (uint32_t)(buf * 64 * PB) * 4;
        const uint32_t vsa = vs_base + (uint32_t)(buf * 64 * PB) * 4;

        // QK strips (pairs) -> f16x2 exp2 -> register-resident P
        uint32_t preg[8][4];
#pragma unroll
        for (int ttp = 0; ttp < 4; ttp++) {
            float sA0[4] = {}, sA1[4] = {}, sB0[4] = {}, sB1[4] = {};
#pragma unroll
            for (int kc = 0; kc < 4; kc++) {
                uint32_t b0, b1, b2, b3;
                ldsm_x4(b0, b1, b2, b3,
                        ksa + (uint32_t)((ttp * 16 + ro) * PB + kc * 8 + co) * 4);
                uint32_t bbA[2] = { b0, b1 };
                uint32_t bbB[2] = { b2, b3 };
                mma_f16(sA0, qa[0][kc], bbA);
                mma_f16(sA1, qa[1][kc], bbA);
                mma_f16(sB0, qa[0][kc], bbB);
                mma_f16(sB1, qa[1][kc], bbB);
            }
            preg[2 * ttp][0]     = hex2(sA0[0], sA0[1]);
            preg[2 * ttp][1]     = hex2(sA0[2], sA0[3]);
            preg[2 * ttp][2]     = hex2(sA1[0], sA1[1]);
            preg[2 * ttp][3]     = hex2(sA1[2], sA1[3]);
            preg[2 * ttp + 1][0] = hex2(sB0[0], sB0[1]);
            preg[2 * ttp + 1][1] = hex2(sB0[2], sB0[3]);
            preg[2 * ttp + 1][2] = hex2(sB1[0], sB1[1]);
            preg[2 * ttp + 1][3] = hex2(sB1[2], sB1[3]);
        }

        // l: pre-sum P fragments across kc (fp16x2 adds), one ones-mma per pair
        {
            uint32_t ps0[4], ps1[4];
            ps0[0] = hadd2(hadd2(preg[0][0], preg[2][0]), hadd2(preg[4][0], preg[6][0]));
            ps0[1] = hadd2(hadd2(preg[0][1], preg[2][1]), hadd2(preg[4][1], preg[6][1]));
            ps0[2] = hadd2(hadd2(preg[1][0], preg[3][0]), hadd2(preg[5][0], preg[7][0]));
            ps0[3] = hadd2(hadd2(preg[1][1], preg[3][1]), hadd2(preg[5][1], preg[7][1]));
            ps1[0] = hadd2(hadd2(preg[0][2], preg[2][2]), hadd2(preg[4][2], preg[6][2]));
            ps1[1] = hadd2(hadd2(preg[0][3], preg[2][3]), hadd2(preg[4][3], preg[6][3]));
            ps1[2] = hadd2(hadd2(preg[1][2], preg[3][2]), hadd2(preg[5][2], preg[7][2]));
            ps1[3] = hadd2(hadd2(preg[1][3], preg[3][3]), hadd2(preg[5][3], preg[7][3]));
            uint32_t bb1[2] = { bone, bone };
            mma_f16(lac0, ps0, bb1);
            mma_f16(lac1, ps1, bb1);
        }

        // O += P V
#pragma unroll
        for (int kc = 0; kc < 4; kc++) {
            uint32_t pa0[4] = { preg[2*kc][0], preg[2*kc][1], preg[2*kc+1][0], preg[2*kc+1][1] };
            uint32_t pa1[4] = { preg[2*kc][2], preg[2*kc][3], preg[2*kc+1][2], preg[2*kc+1][3] };
#pragma unroll
            for (int ttp = 0; ttp < 4; ttp++) {
                uint32_t b0, b1, b2, b3;
                ldsm_x4(b0, b1, b2, b3,
                        vsa + (uint32_t)((ttp * 16 + ro) * PB + kc * 8 + co) * 4);
                uint32_t bbA[2] = { b0, b1 };
                uint32_t bbB[2] = { b2, b3 };
                mma_f16(o0[2 * ttp],     pa0, bbA);
                mma_f16(o1[2 * ttp],     pa1, bbA);
                mma_f16(o0[2 * ttp + 1], pa0, bbB);
                mma_f16(o1[2 * ttp + 1], pa1, bbB);
            }
        }
    }

    const size_t rbase = (size_t)b * SEQ + q0;
    if (c == 0) {
        float* lp = g_lpart + (size_t)split * (BATCH * SEQ) + rbase;
        lp[qr]      = lac0[0];
        lp[qr + 8]  = lac0[2];
        lp[qr + 16] = lac1[0];
        lp[qr + 24] = lac1[2];
    }
    // O partials packed fp16x2: u32 col index uc = tt*4 + c -> out cols 2uc, 2uc+1
    uint32_t* op = g_opart + (size_t)split * (BATCH * SEQ * 32) + rbase * 32;
#pragma unroll
    for (int tt = 0; tt < 8; tt++) {
        int uc = tt * 4 + c;
        op[(size_t)(qr)      * 32 + uc] = packh(o0[tt][0], o0[tt][1]);
        op[(size_t)(qr + 8)  * 32 + uc] = packh(o0[tt][2], o0[tt][3]);
        op[(size_t)(qr + 16) * 32 + uc] = packh(o1[tt][0], o1[tt][1]);
        op[(size_t)(qr + 24) * 32 + uc] = packh(o1[tt][2], o1[tt][3]);
    }
}

// ---------------------------------------------------------------------------
// Kernel 3: combine fp16 split partials: out = sum_s O_s / sum_s l_s
// ---------------------------------------------------------------------------
__global__ void __launch_bounds__(256) combine_kernel(float* __restrict__ out)
{
    int idx = blockIdx.x * 256 + threadIdx.x;          // u32-quad index
    if (idx >= BATCH * SEQ * 8) return;
    int row = idx >> 3;
    int uc0 = (idx & 7) * 4;
    float lsum = 0.0f;
#pragma unroll
    for (int s = 0; s < SPLITS; s++) lsum += g_lpart[(size_t)s * (BATCH * SEQ) + row];
    float inv = 1.0f / lsum;
    float acc[8] = {};
#pragma unroll
    for (int s = 0; s < SPLITS; s++) {
        uint4 u = *(const uint4*)&g_opart[(size_t)s * (BATCH * SEQ * 32) +
                                          (size_t)row * 32 + uc0];
        float2 f;
        f = unpackh(u.x); acc[0] += f.x; acc[1] += f.y;
        f = unpackh(u.y); acc[2] += f.x; acc[3] += f.y;
        f = unpackh(u.z); acc[4] += f.x; acc[5] += f.y;
        f = unpackh(u.w); acc[6] += f.x; acc[7] += f.y;
    }
    float* ob = out + (size_t)row * HDIM + uc0 * 2;
    float4 o0 = make_float4(acc[0] * inv, acc[1] * inv, acc[2] * inv, acc[3] * inv);
    float4 o1 = make_float4(acc[4] * inv, acc[5] * inv, acc[6] * inv, acc[7] * inv);
    *(float4*)&ob[0] = o0;
    *(float4*)&ob[4] = o1;
}

// ---------------------------------------------------------------------------
extern "C" void kernel_launch(void* const* d_in, const int* in_sizes, int n_in,
                              void* d_out, int out_size)
{
    const float* x  = (const float*)d_in[0];
    const float* Wq = (const float*)d_in[1];
    const float* bq = (const float*)d_in[2];
    const float* Wk = (const float*)d_in[3];
    const float* bk = (const float*)d_in[4];
    const float* Wv = (const float*)d_in[5];
    const float* bv = (const float*)d_in[6];
    float* out = (float*)d_out;

    wconv_kernel<<<(192 * 384 + 255) / 256, 256>>>(Wq, Wk, Wv);

    cudaFuncSetAttribute(qkv_kernel, cudaFuncAttributeMaxDynamicSharedMemorySize,
                         QKV_SMEM);
    qkv_kernel<<<(BATCH * SEQ) / 64, 128, QKV_SMEM>>>(x, bq, bk, bv);

    dim3 grid(SEQ / 128, BATCH, SPLITS);
    attn_kernel<<<grid, 128>>>();

    combine_kernel<<<(BATCH * SEQ * 8 + 255) / 256, 256>>>(out);
}